// round 15
// baseline (speedup 1.0000x reference)
#include <cuda_runtime.h>
#include <cuda_fp16.h>
#include <cstdint>

// ============================================================================
// Problem constants (dataset: n1=n2=8192, d=256)
// ============================================================================
#define D_DIM 256
#define N_MAX 8192

// Scratch (allocation-free rule: __device__ globals)
// Single-pass scheme: dot ~= ah*bh (fp16 rounded operands, fp32 accum).
__device__ __align__(128) __half g_ah[N_MAX * D_DIM];
__device__ __align__(128) __half g_bh[N_MAX * D_DIM];
__device__ __align__(128) float  g_sq1[N_MAX];
__device__ __align__(128) float  g_sq2[N_MAX];
__device__ __align__(128) float  g_part[256 * D_DIM];
__device__ __align__(128) float  g_adj[D_DIM];
__device__ __align__(128) float  g_rls[D_DIM];

__device__ __forceinline__ uint32_t h2_to_u32(__half2 h) {
    union { __half2 h; uint32_t u; } c; c.h = h; return c.u;
}

// ============================================================================
// Portable PTX helpers (sm_80-era ISA only: cp.async / ldmatrix / mma.sync)
// ============================================================================
__device__ __forceinline__ uint32_t smem_u32(const void* p) {
    uint32_t a;
    asm("{ .reg .u64 t; cvta.to.shared.u64 t, %1; cvt.u32.u64 %0, t; }"
        : "=r"(a) : "l"(p));
    return a;
}

__device__ __forceinline__ void cp16(uint32_t dst, const void* src) {
    asm volatile("cp.async.cg.shared.global [%0], [%1], 16;"
                 :: "r"(dst), "l"(src) : "memory");
}
#define CP_COMMIT() asm volatile("cp.async.commit_group;" ::: "memory")
#define CP_WAIT0()  asm volatile("cp.async.wait_group 0;" ::: "memory")

#define LDSM_X4(r, addr) \
    asm volatile("ldmatrix.sync.aligned.m8n8.x4.shared.b16 {%0,%1,%2,%3}, [%4];" \
                 : "=r"((r)[0]), "=r"((r)[1]), "=r"((r)[2]), "=r"((r)[3]) \
                 : "r"(addr))

// fp32-accumulator HMMA
__device__ __forceinline__ void mma16816_f32(float* c, const uint32_t* a,
                                             const uint32_t* b) {
    asm volatile(
        "mma.sync.aligned.m16n8k16.row.col.f32.f16.f16.f32 "
        "{%0,%1,%2,%3}, {%4,%5,%6,%7}, {%8,%9}, {%0,%1,%2,%3};"
        : "+f"(c[0]), "+f"(c[1]), "+f"(c[2]), "+f"(c[3])
        : "r"(a[0]), "r"(a[1]), "r"(a[2]), "r"(a[3]),
          "r"(b[0]), "r"(b[1]));
}

__device__ __forceinline__ float sqrt_approx(float x) {
    float r; asm("sqrt.approx.f32 %0, %1;" : "=f"(r) : "f"(x)); return r;
}
__device__ __forceinline__ float ex2_approx(float x) {
    float r; asm("ex2.approx.f32 %0, %1;" : "=f"(r) : "f"(x)); return r;
}

// streaming (evict-first) 8B store: output is write-once, keep tiles in L2
__device__ __forceinline__ void stg_cs_f2(float* p, float x, float y) {
    float2 v = make_float2(x, y);
    asm volatile("st.global.cs.v2.f32 [%0], {%1, %2};"
                 :: "l"(p), "f"(v.x), "f"(v.y) : "memory");
}

// ============================================================================
// Prep kernels (exactly 3 launches before the GEMM -> ncu -s5 hits the GEMM)
// ============================================================================
__global__ void k_mean_partial(const float* __restrict__ x1, int n1) {
    int d = threadIdx.x, b = blockIdx.x;
    int r0 = b * 32;
    float s = 0.f;
#pragma unroll 8
    for (int r = 0; r < 32; r++)
        s += x1[(size_t)(r0 + r) * D_DIM + d];
    g_part[b * D_DIM + d] = s;
}

__global__ void k_mean_final(const float* __restrict__ ls, int n1) {
    int d = threadIdx.x;
    float s = 0.f;
    for (int b = 0; b < 256; b++) s += g_part[b * D_DIM + d];
    g_adj[d] = s / (float)n1;
    g_rls[d] = 1.0f / ls[d];
}

// Center, scale, round to fp16; row sqnorm from EXACT fp32 values.
__global__ void k_normalize2(const float* __restrict__ x1,
                             const float* __restrict__ x2, int n1, int ntot) {
    int wid  = threadIdx.x >> 5;
    int lane = threadIdx.x & 31;
    int grow = blockIdx.x * 8 + wid;
    if (grow >= ntot) return;

    int which = (grow >= n1);
    int row   = which ? (grow - n1) : grow;
    const float* x = which ? x2 : x1;
    __half* hi = which ? g_bh : g_ah;
    float*  sq = which ? g_sq2 : g_sq1;

    const float4* xr = reinterpret_cast<const float4*>(x + (size_t)row * D_DIM);
    const float4* aj = reinterpret_cast<const float4*>(g_adj);
    const float4* rl = reinterpret_cast<const float4*>(g_rls);

    float ssum = 0.f;
    uint4 packh;
    uint32_t* ph = reinterpret_cast<uint32_t*>(&packh);
#pragma unroll
    for (int g = 0; g < 2; g++) {
        int v4 = lane * 2 + g;
        float4 xv = xr[v4];
        float4 av = aj[v4];
        float4 rv = rl[v4];
        float vv[4] = { (xv.x - av.x) * rv.x, (xv.y - av.y) * rv.y,
                        (xv.z - av.z) * rv.z, (xv.w - av.w) * rv.w };
#pragma unroll
        for (int e = 0; e < 4; e += 2) {
            float v0 = vv[e], v1 = vv[e + 1];
            ph[g * 2 + e / 2] = h2_to_u32(__halves2half2(__float2half_rn(v0),
                                                         __float2half_rn(v1)));
            ssum = fmaf(v0, v0, ssum);
            ssum = fmaf(v1, v1, ssum);
        }
    }
    reinterpret_cast<uint4*>(hi + (size_t)row * D_DIM)[lane] = packh;
#pragma unroll
    for (int o = 16; o > 0; o >>= 1)
        ssum += __shfl_xor_sync(0xffffffffu, ssum, o);
    if (lane == 0) sq[row] = ssum;
}

// ============================================================================
// Fused GEMM + Matern epilogue (mma.sync m16n8k16, single fp16 pass)
//
// CTA tile 256x128, 512 threads (16 warps, 4x4), warp tile 64x32, occ 1
// (same 16 warps/SM as the proven config, but: L2 tile traffic -25%,
//  half as many CTAs -> half the prologue load stalls, 2x A reuse).
// K = 256 in 4 chunks of 64, double-buffered, ONE __syncthreads per chunk.
// ROW_B=144: 8-row LDSM covers all 32 banks exactly once (conflict-free).
// R13 burst LDSM schedule (measured best); streaming epilogue stores.
// ============================================================================
#define ROW_B    144                   // 128B data + 16B pad per k64 row
#define A_TILE   (256 * ROW_B)         // 36864 B
#define B_TILE   (128 * ROW_B)         // 18432 B
#define STAGE_B  (A_TILE + B_TILE)     // 55296 B
#define SMEM_REQ (2 * STAGE_B + 2048)  // 112640 B (occ 1: fits 228KB)

__global__ void __launch_bounds__(512, 1)
k_matern_gemm(float* __restrict__ out, int n2) {
    extern __shared__ char smem_raw[];
    uint32_t sbase_u = smem_u32(smem_raw);
    uint32_t abase = (sbase_u + 127u) & ~127u;
    char* ap = smem_raw + (abase - sbase_u);

    const int tid  = threadIdx.x;
    const int lane = tid & 31;
    const int wid  = tid >> 5;
    const int wm   = wid >> 2;   // 0..3 : 64-row slice of 256
    const int wn   = wid & 3;    // 0..3 : 32-col slice of 128
    const int bX   = blockIdx.x;
    const int bY   = blockIdx.y;

    float* s_sq1 = reinterpret_cast<float*>(ap + 2 * STAGE_B);          // 256
    float* s_sq2 = reinterpret_cast<float*>(ap + 2 * STAGE_B + 1024);   // 128
    if (tid < 256) s_sq1[tid] = 3.0f * g_sq1[(size_t)bY * 256 + tid];
    else if (tid < 384) s_sq2[tid - 256] = 3.0f * g_sq2[(size_t)bX * 128 + (tid - 256)];

    const int ld_row = tid >> 3;           // 0..63
    const int ld_seg = tid & 7;
    const __half* srcA = g_ah + (size_t)bY * 256 * D_DIM;
    const __half* srcB = g_bh + (size_t)bX * 128 * D_DIM;

    // one k64 chunk: A 256 rows x 8 segs + B 128 rows x 8 segs = 6 cp16/thr
    auto load_stage = [&](int buf, int kc) {
        uint32_t sbuf = abase + (uint32_t)buf * STAGE_B;
        const __half* sa = srcA + kc * 64;
        const __half* sb = srcB + kc * 64;
#pragma unroll
        for (int i = 0; i < 4; i++) {
            int row = ld_row + i * 64;          // 0..255
            cp16(sbuf + (uint32_t)(row * ROW_B + ld_seg * 16),
                 sa + (size_t)row * D_DIM + ld_seg * 8);
        }
#pragma unroll
        for (int i = 0; i < 2; i++) {
            int row = ld_row + i * 64;          // 0..127
            cp16(sbuf + A_TILE + (uint32_t)(row * ROW_B + ld_seg * 16),
                 sb + (size_t)row * D_DIM + ld_seg * 8);
        }
    };

    float acc[4][4][4];                 // [mt 16-row][n8 col][4], fp32
#pragma unroll
    for (int i = 0; i < 4; i++)
#pragma unroll
        for (int j = 0; j < 4; j++)
#pragma unroll
            for (int e = 0; e < 4; e++) acc[i][j][e] = 0.f;

    load_stage(0, 0);
    CP_COMMIT();

    const int arow = wm * 64 + (lane & 15);
    const int t    = lane >> 3;
    const int bn   = wn * 32 + ((t >> 1) << 3) + (lane & 7);

    const int NCHUNK = D_DIM / 64;   // 4
    for (int c = 0; c < NCHUNK; c++) {
        CP_WAIT0();                  // chunk c resident
        __syncthreads();             // all warps done with chunk c-1 buffer
        if (c + 1 < NCHUNK) {
            load_stage((c + 1) & 1, c + 1);
            CP_COMMIT();
        }

        uint32_t sA = abase + (uint32_t)(c & 1) * STAGE_B;
        uint32_t sB = sA + A_TILE;

#pragma unroll
        for (int s = 0; s < 4; s++) {            // four k16 steps per 64-chunk
            uint32_t ah[4][4], bh[2][4];
            int ag = s * 2 + (lane >> 4);
            int bg = s * 2 + (t & 1);
#pragma unroll
            for (int mt = 0; mt < 4; mt++)
                LDSM_X4(ah[mt], sA + (uint32_t)((arow + mt * 16) * ROW_B + ag * 16));
#pragma unroll
            for (int ng = 0; ng < 2; ng++)
                LDSM_X4(bh[ng], sB + (uint32_t)((bn + ng * 16) * ROW_B + bg * 16));
#pragma unroll
            for (int mt = 0; mt < 4; mt++)
#pragma unroll
                for (int ng = 0; ng < 2; ng++) {
                    mma16816_f32(acc[mt][ng * 2],     ah[mt], bh[ng]);
                    mma16816_f32(acc[mt][ng * 2 + 1], ah[mt], bh[ng] + 2);
                }
        }
    }

    // ---- fused Matern epilogue: d2' = 3*d2 ; t = sqrt(d2') = sqrt3*dist ----
    const int r0 = lane >> 2;
    const int c0 = 2 * (lane & 3);
#pragma unroll
    for (int mt = 0; mt < 4; mt++) {
        int row_l = wm * 64 + mt * 16 + r0;
        int row_g = bY * 256 + row_l;
        float sqa0 = s_sq1[row_l];
        float sqa8 = s_sq1[row_l + 8];
        float* orow0 = out + (size_t)row_g * (size_t)n2 + (size_t)bX * 128;
        float* orow8 = orow0 + 8u * (size_t)n2;
#pragma unroll
        for (int nt = 0; nt < 4; nt++) {
            int col_l = wn * 32 + nt * 8 + c0;
            float sqb0 = s_sq2[col_l];
            float sqb1 = s_sq2[col_l + 1];
            const float* a = acc[mt][nt];
            float sqs[4]  = { sqa0 + sqb0, sqa0 + sqb1, sqa8 + sqb0, sqa8 + sqb1 };
            float res[4];
#pragma unroll
            for (int e = 0; e < 4; e++) {
                float d2p = fmaf(-6.f, a[e], sqs[e]);     // 3*d2
                d2p = fmaxf(d2p, 3e-30f);                 // dist >= 1e-15
                float t2 = sqrt_approx(d2p);              // sqrt3 * dist
                res[e] = (1.f + t2) * ex2_approx(-1.44269504f * t2);
            }
            stg_cs_f2(orow0 + col_l, res[0], res[1]);
            stg_cs_f2(orow8 + col_l, res[2], res[3]);
        }
    }
}

// ============================================================================
// kernel_launch
// ============================================================================
extern "C" void kernel_launch(void* const* d_in, const int* in_sizes, int n_in,
                              void* d_out, int out_size) {
    const float* x1 = (const float*)d_in[0];
    const float* x2 = (const float*)d_in[1];
    const float* ls = (const float*)d_in[2];
    float* out = (float*)d_out;

    int d  = in_sizes[2];            // 256
    int n1 = in_sizes[0] / d;        // 8192
    int n2 = in_sizes[1] / d;        // 8192

    k_mean_partial<<<n1 / 32, D_DIM>>>(x1, n1);
    k_mean_final<<<1, D_DIM>>>(ls, n1);
    k_normalize2<<<(n1 + n2) / 8, 256>>>(x1, x2, n1, n1 + n2);

    static bool attr_set = false;
    if (!attr_set) {
        cudaFuncSetAttribute(k_matern_gemm,
                             cudaFuncAttributeMaxDynamicSharedMemorySize, SMEM_REQ);
        attr_set = true;
    }
    dim3 grid(n2 / 128, n1 / 256);
    k_matern_gemm<<<grid, 512, SMEM_REQ>>>(out, n2);
}

// round 16
// speedup vs baseline: 1.1607x; 1.1607x over previous
#include <cuda_runtime.h>
#include <cuda_fp16.h>
#include <cstdint>

// ============================================================================
// Problem constants (dataset: n1=n2=8192, d=256)
// ============================================================================
#define D_DIM 256
#define N_MAX 8192

// Scratch (allocation-free rule: __device__ globals)
// Single-pass scheme: dot ~= ah*bh (fp16 rounded operands, fp32 accum).
__device__ __align__(128) __half g_ah[N_MAX * D_DIM];
__device__ __align__(128) __half g_bh[N_MAX * D_DIM];
__device__ __align__(128) float  g_sq1[N_MAX];
__device__ __align__(128) float  g_sq2[N_MAX];
__device__ __align__(128) float  g_part[256 * D_DIM];
__device__ __align__(128) float  g_adj[D_DIM];
__device__ __align__(128) float  g_rls[D_DIM];

__device__ __forceinline__ uint32_t h2_to_u32(__half2 h) {
    union { __half2 h; uint32_t u; } c; c.h = h; return c.u;
}

// ============================================================================
// Portable PTX helpers (sm_80-era ISA only: cp.async / ldmatrix / mma.sync)
// ============================================================================
__device__ __forceinline__ uint32_t smem_u32(const void* p) {
    uint32_t a;
    asm("{ .reg .u64 t; cvta.to.shared.u64 t, %1; cvt.u32.u64 %0, t; }"
        : "=r"(a) : "l"(p));
    return a;
}

__device__ __forceinline__ void cp16(uint32_t dst, const void* src) {
    asm volatile("cp.async.cg.shared.global [%0], [%1], 16;"
                 :: "r"(dst), "l"(src) : "memory");
}
#define CP_COMMIT() asm volatile("cp.async.commit_group;" ::: "memory")
#define CP_WAIT0()  asm volatile("cp.async.wait_group 0;" ::: "memory")

#define LDSM_X4(r, addr) \
    asm volatile("ldmatrix.sync.aligned.m8n8.x4.shared.b16 {%0,%1,%2,%3}, [%4];" \
                 : "=r"((r)[0]), "=r"((r)[1]), "=r"((r)[2]), "=r"((r)[3]) \
                 : "r"(addr))

// fp32-accumulator HMMA
__device__ __forceinline__ void mma16816_f32(float* c, const uint32_t* a,
                                             const uint32_t* b) {
    asm volatile(
        "mma.sync.aligned.m16n8k16.row.col.f32.f16.f16.f32 "
        "{%0,%1,%2,%3}, {%4,%5,%6,%7}, {%8,%9}, {%0,%1,%2,%3};"
        : "+f"(c[0]), "+f"(c[1]), "+f"(c[2]), "+f"(c[3])
        : "r"(a[0]), "r"(a[1]), "r"(a[2]), "r"(a[3]),
          "r"(b[0]), "r"(b[1]));
}

__device__ __forceinline__ float sqrt_approx(float x) {
    float r; asm("sqrt.approx.f32 %0, %1;" : "=f"(r) : "f"(x)); return r;
}
__device__ __forceinline__ float ex2_approx(float x) {
    float r; asm("ex2.approx.f32 %0, %1;" : "=f"(r) : "f"(x)); return r;
}

// streaming (evict-first) 8B store: output is write-once, keep tiles in L2
__device__ __forceinline__ void stg_cs_f2(float* p, float x, float y) {
    float2 v = make_float2(x, y);
    asm volatile("st.global.cs.v2.f32 [%0], {%1, %2};"
                 :: "l"(p), "f"(v.x), "f"(v.y) : "memory");
}

// ============================================================================
// Prep kernels (exactly 3 launches before the GEMM -> ncu -s5 hits the GEMM)
// ============================================================================
__global__ void k_mean_partial(const float* __restrict__ x1, int n1) {
    int d = threadIdx.x, b = blockIdx.x;
    int r0 = b * 32;
    float s = 0.f;
#pragma unroll 8
    for (int r = 0; r < 32; r++)
        s += x1[(size_t)(r0 + r) * D_DIM + d];
    g_part[b * D_DIM + d] = s;
}

__global__ void k_mean_final(const float* __restrict__ ls, int n1) {
    int d = threadIdx.x;
    float s = 0.f;
    for (int b = 0; b < 256; b++) s += g_part[b * D_DIM + d];
    g_adj[d] = s / (float)n1;
    g_rls[d] = 1.0f / ls[d];
}

// Center, scale, round to fp16; row sqnorm from EXACT fp32 values.
__global__ void k_normalize2(const float* __restrict__ x1,
                             const float* __restrict__ x2, int n1, int ntot) {
    int wid  = threadIdx.x >> 5;
    int lane = threadIdx.x & 31;
    int grow = blockIdx.x * 8 + wid;
    if (grow >= ntot) return;

    int which = (grow >= n1);
    int row   = which ? (grow - n1) : grow;
    const float* x = which ? x2 : x1;
    __half* hi = which ? g_bh : g_ah;
    float*  sq = which ? g_sq2 : g_sq1;

    const float4* xr = reinterpret_cast<const float4*>(x + (size_t)row * D_DIM);
    const float4* aj = reinterpret_cast<const float4*>(g_adj);
    const float4* rl = reinterpret_cast<const float4*>(g_rls);

    float ssum = 0.f;
    uint4 packh;
    uint32_t* ph = reinterpret_cast<uint32_t*>(&packh);
#pragma unroll
    for (int g = 0; g < 2; g++) {
        int v4 = lane * 2 + g;
        float4 xv = xr[v4];
        float4 av = aj[v4];
        float4 rv = rl[v4];
        float vv[4] = { (xv.x - av.x) * rv.x, (xv.y - av.y) * rv.y,
                        (xv.z - av.z) * rv.z, (xv.w - av.w) * rv.w };
#pragma unroll
        for (int e = 0; e < 4; e += 2) {
            float v0 = vv[e], v1 = vv[e + 1];
            ph[g * 2 + e / 2] = h2_to_u32(__halves2half2(__float2half_rn(v0),
                                                         __float2half_rn(v1)));
            ssum = fmaf(v0, v0, ssum);
            ssum = fmaf(v1, v1, ssum);
        }
    }
    reinterpret_cast<uint4*>(hi + (size_t)row * D_DIM)[lane] = packh;
#pragma unroll
    for (int o = 16; o > 0; o >>= 1)
        ssum += __shfl_xor_sync(0xffffffffu, ssum, o);
    if (lane == 0) sq[row] = ssum;
}

// ============================================================================
// Fused GEMM + Matern epilogue (mma.sync m16n8k16, single fp16 pass)
//
// Empirical-best recomposition:
//  - R13 GEMM config: CTA 128x128, 8 warps (2x4), warp 64x32, occ 2,
//    k64 chunks double-buffered, ONE __syncthreads per chunk (4 total),
//    ROW_B=144, BURST LDSM schedule (measured faster than interleave).
//  - R14 extras: loop-carried cp.async pointers, st.global.cs stores.
// ============================================================================
#define ROW_B    144                   // 128B data + 16B pad per k64 row
#define TILE_B   (128 * ROW_B)         // 18432 B per tile
#define STAGE_B  (2 * TILE_B)          // Ah | Bh = 36864 B
#define SMEM_REQ (2 * STAGE_B + 1536)  // 75264 B

__global__ void __launch_bounds__(256, 2)
k_matern_gemm(float* __restrict__ out, int n2) {
    extern __shared__ char smem_raw[];
    uint32_t sbase_u = smem_u32(smem_raw);
    uint32_t abase = (sbase_u + 127u) & ~127u;
    char* ap = smem_raw + (abase - sbase_u);

    const int tid  = threadIdx.x;
    const int lane = tid & 31;
    const int wid  = tid >> 5;
    const int wm   = wid >> 2;   // 0..1 : 64-row slice
    const int wn   = wid & 3;    // 0..3 : 32-col slice
    const int bX   = blockIdx.x;
    const int bY   = blockIdx.y;

    float* s_sq1 = reinterpret_cast<float*>(ap + 2 * STAGE_B);
    float* s_sq2 = reinterpret_cast<float*>(ap + 2 * STAGE_B + 512);
    if (tid < 128) {
        s_sq1[tid] = 3.0f * g_sq1[(size_t)bY * 128 + tid];   // pre-scaled by 3
        s_sq2[tid] = 3.0f * g_sq2[(size_t)bX * 128 + tid];
    }

    // loop-carried cp.async source addressing
    const int ld_row = tid >> 3;           // 0..31 base row
    const int ld_seg = tid & 7;
    const __half* srcA = g_ah + (size_t)bY * 128 * D_DIM;
    const __half* srcB = g_bh + (size_t)bX * 128 * D_DIM;

    auto load_stage = [&](int buf, int kc) {
        uint32_t sbuf = abase + (uint32_t)buf * STAGE_B;
        const __half* sa = srcA + kc * 64;
        const __half* sb = srcB + kc * 64;
#pragma unroll
        for (int i = 0; i < 4; i++) {
            int row = ld_row + i * 32;          // 0..127
            uint32_t doff = (uint32_t)(row * ROW_B + ld_seg * 16);
            size_t   soff = (size_t)row * D_DIM + ld_seg * 8;
            cp16(sbuf + doff, sa + soff);
            cp16(sbuf + TILE_B + doff, sb + soff);
        }
    };

    float acc[4][4][4];                 // [mt 16-row][n8 col][4], fp32
#pragma unroll
    for (int i = 0; i < 4; i++)
#pragma unroll
        for (int j = 0; j < 4; j++)
#pragma unroll
            for (int e = 0; e < 4; e++) acc[i][j][e] = 0.f;

    load_stage(0, 0);
    CP_COMMIT();

    const int arow = wm * 64 + (lane & 15);
    const int t    = lane >> 3;
    const int bn   = wn * 32 + ((t >> 1) << 3) + (lane & 7);

    const int NCHUNK = D_DIM / 64;   // 4
    for (int c = 0; c < NCHUNK; c++) {
        CP_WAIT0();                  // chunk c resident
        __syncthreads();             // all warps done with chunk c-1 buffer
        if (c + 1 < NCHUNK) {
            load_stage((c + 1) & 1, c + 1);
            CP_COMMIT();
        }

        uint32_t sA = abase + (uint32_t)(c & 1) * STAGE_B;
        uint32_t sB = sA + TILE_B;

#pragma unroll
        for (int s = 0; s < 4; s++) {            // four k16 steps per 64-chunk
            uint32_t ah[4][4], bh[2][4];
            int ag = s * 2 + (lane >> 4);
            int bg = s * 2 + (t & 1);
#pragma unroll
            for (int mt = 0; mt < 4; mt++)
                LDSM_X4(ah[mt], sA + (uint32_t)((arow + mt * 16) * ROW_B + ag * 16));
#pragma unroll
            for (int ng = 0; ng < 2; ng++)
                LDSM_X4(bh[ng], sB + (uint32_t)((bn + ng * 16) * ROW_B + bg * 16));
#pragma unroll
            for (int mt = 0; mt < 4; mt++)
#pragma unroll
                for (int ng = 0; ng < 2; ng++) {
                    mma16816_f32(acc[mt][ng * 2],     ah[mt], bh[ng]);
                    mma16816_f32(acc[mt][ng * 2 + 1], ah[mt], bh[ng] + 2);
                }
        }
    }

    // ---- fused Matern epilogue: d2' = 3*d2 ; t = sqrt(d2') = sqrt3*dist ----
    const int r0 = lane >> 2;
    const int c0 = 2 * (lane & 3);
#pragma unroll
    for (int mt = 0; mt < 4; mt++) {
        int row_l = wm * 64 + mt * 16 + r0;
        int row_g = bY * 128 + row_l;
        float sqa0 = s_sq1[row_l];
        float sqa8 = s_sq1[row_l + 8];
        float* orow0 = out + (size_t)row_g * (size_t)n2 + (size_t)bX * 128;
        float* orow8 = orow0 + 8u * (size_t)n2;
#pragma unroll
        for (int nt = 0; nt < 4; nt++) {
            int col_l = wn * 32 + nt * 8 + c0;
            float sqb0 = s_sq2[col_l];
            float sqb1 = s_sq2[col_l + 1];
            const float* a = acc[mt][nt];
            float sqs[4]  = { sqa0 + sqb0, sqa0 + sqb1, sqa8 + sqb0, sqa8 + sqb1 };
            float res[4];
#pragma unroll
            for (int e = 0; e < 4; e++) {
                float d2p = fmaf(-6.f, a[e], sqs[e]);     // 3*d2
                d2p = fmaxf(d2p, 3e-30f);                 // dist >= 1e-15
                float t2 = sqrt_approx(d2p);              // sqrt3 * dist
                res[e] = (1.f + t2) * ex2_approx(-1.44269504f * t2);
            }
            stg_cs_f2(orow0 + col_l, res[0], res[1]);
            stg_cs_f2(orow8 + col_l, res[2], res[3]);
        }
    }
}

// ============================================================================
// kernel_launch
// ============================================================================
extern "C" void kernel_launch(void* const* d_in, const int* in_sizes, int n_in,
                              void* d_out, int out_size) {
    const float* x1 = (const float*)d_in[0];
    const float* x2 = (const float*)d_in[1];
    const float* ls = (const float*)d_in[2];
    float* out = (float*)d_out;

    int d  = in_sizes[2];            // 256
    int n1 = in_sizes[0] / d;        // 8192
    int n2 = in_sizes[1] / d;        // 8192

    k_mean_partial<<<n1 / 32, D_DIM>>>(x1, n1);
    k_mean_final<<<1, D_DIM>>>(ls, n1);
    k_normalize2<<<(n1 + n2) / 8, 256>>>(x1, x2, n1, n1 + n2);

    static bool attr_set = false;
    if (!attr_set) {
        cudaFuncSetAttribute(k_matern_gemm,
                             cudaFuncAttributeMaxDynamicSharedMemorySize, SMEM_REQ);
        attr_set = true;
    }
    dim3 grid(n2 / 128, n1 / 128);
    k_matern_gemm<<<grid, 256, SMEM_REQ>>>(out, n2);
}